// round 7
// baseline (speedup 1.0000x reference)
#include <cuda_runtime.h>
#include <cuda_bf16.h>
#include <math.h>
#include <stdint.h>

// ---------------- model constants ----------------
#define B_    2
#define N_    1024
#define D_    256
#define H_    8
#define DH_   32
#define K_    4
#define IN_   1024
#define V_    32000
#define CK_   3
#define MAXL_ 8
#define TRUNC_ 4
#define BN_   (B_ * N_)
#define QKVS  (3 * D_)      // row stride of fused qkv buffer

// ---------------- scratch (device globals, no allocs) ----------------
__device__ float g_X  [BN_ * D_];
__device__ float g_Q  [BN_ * D_];
__device__ float g_Hc [BN_ * D_];
__device__ float g_qkv[BN_ * QKVS];
__device__ float g_cmv[BN_ * D_];
__device__ float g_hn [BN_ * D_];
__device__ float g_gu [BN_ * 2 * IN_];
__device__ float g_hc2[BN_ * IN_];
__device__ float g_qn [BN_ * D_];

// ---------------- bf16 helpers ----------------
__device__ __forceinline__ uint32_t pack_bf2(float a, float b) {
    __nv_bfloat162 t = __floats2bfloat162_rn(a, b);   // x = a (low), y = b (high)
    return *reinterpret_cast<uint32_t*>(&t);
}
__device__ __forceinline__ void split_bf(float v, __nv_bfloat16& h, __nv_bfloat16& l) {
    h = __float2bfloat16_rn(v);
    l = __float2bfloat16_rn(v - __bfloat162float(h));
}

__device__ __forceinline__ void mma16(float* c, const uint32_t* a, uint32_t b0, uint32_t b1) {
    asm volatile("mma.sync.aligned.m16n8k16.row.col.f32.bf16.bf16.f32 "
                 "{%0,%1,%2,%3}, {%4,%5,%6,%7}, {%8,%9}, {%0,%1,%2,%3};"
                 : "+f"(c[0]), "+f"(c[1]), "+f"(c[2]), "+f"(c[3])
                 : "r"(a[0]), "r"(a[1]), "r"(a[2]), "r"(a[3]), "r"(b0), "r"(b1));
}

// ---------------- tf32 helpers (LM head only) ----------------
__device__ __forceinline__ void split2(float x, uint32_t& hi, uint32_t& lo) {
    uint32_t h;
    asm("cvt.rna.tf32.f32 %0, %1;" : "=r"(h) : "f"(x));
    float r = x - __uint_as_float(h);
    uint32_t l;
    asm("cvt.rna.tf32.f32 %0, %1;" : "=r"(l) : "f"(r));
    hi = h; lo = l;
}
__device__ __forceinline__ void mma8(float* c, const uint32_t* a, uint32_t b0, uint32_t b1) {
    asm volatile("mma.sync.aligned.m16n8k8.row.col.f32.tf32.tf32.f32 "
                 "{%0,%1,%2,%3}, {%4,%5,%6,%7}, {%8,%9}, {%0,%1,%2,%3};"
                 : "+f"(c[0]), "+f"(c[1]), "+f"(c[2]), "+f"(c[3])
                 : "r"(a[0]), "r"(a[1]), "r"(a[2]), "r"(a[3]), "r"(b0), "r"(b1));
}

// ---------------- misc helpers ----------------
__device__ __forceinline__ float blockReduceSum256(float v) {
    __shared__ float sh[8];
    int lane = threadIdx.x & 31;
    int wid  = threadIdx.x >> 5;
#pragma unroll
    for (int o = 16; o > 0; o >>= 1) v += __shfl_down_sync(0xffffffffu, v, o);
    __syncthreads();
    if (lane == 0) sh[wid] = v;
    __syncthreads();
    float t = 0.f;
#pragma unroll
    for (int i = 0; i < 8; i++) t += sh[i];
    return t;
}

// ---------------- embedding + positional ----------------
__global__ void embed_kernel(const int* __restrict__ ids,
                             const float* __restrict__ emb,
                             const float* __restrict__ pos,
                             float* __restrict__ X) {
    int row = blockIdx.x;
    int d   = threadIdx.x;
    int n   = row & (N_ - 1);
    int id  = ids[row];
    X[(size_t)row * D_ + d] = emb[(size_t)id * D_ + d] + pos[(size_t)n * D_ + d];
}

// ---------------- layernorm ----------------
__global__ void ln_kernel(const float* __restrict__ in,
                          const float* __restrict__ w,
                          const float* __restrict__ b,
                          const float* __restrict__ addX,
                          float* __restrict__ out,
                          float* __restrict__ out2) {
    int row = blockIdx.x;
    int d   = threadIdx.x;
    float x  = in[(size_t)row * D_ + d];
    float mu = blockReduceSum256(x) * (1.f / D_);
    float dx = x - mu;
    float var = blockReduceSum256(dx * dx) * (1.f / D_);
    float y = dx * rsqrtf(var + 1e-5f) * w[d] + b[d];
    if (addX) y += addX[(size_t)row * D_ + d];
    out[(size_t)row * D_ + d] = y;
    if (out2) out2[(size_t)row * D_ + d] = y;
}

// ============================================================================
// bf16x3 GEMM, 64x64x32 tiles, 256 threads (8 warps: 2m x 4n, warp tile 32x16)
// Supports up to 3 weight matrices (QKV fusion): block column group selects B.
// epi: 0 none, 1 elu(x)+1, 2 aux + softplus(dts[kidx])*x, 3 aux + x
// ============================================================================
#define GB3_SMEM ((4 * 64 * 17) * 4)

__global__ void __launch_bounds__(256)
gemm_b3(const float* __restrict__ A,
        const float* __restrict__ B0, const float* __restrict__ B1,
        const float* __restrict__ B2,
        float* __restrict__ C, int Kd, int N, int nblk, int ldc,
        int e0, int e1, int e2,
        const float* __restrict__ aux, const float* __restrict__ dts, int kidx)
{
    extern __shared__ uint32_t sh[];
    uint32_t* Ah = sh;                 // [64][17] packed bf16 pairs (k-major)
    uint32_t* Al = Ah + 64 * 17;
    uint32_t* Bh = Al + 64 * 17;       // [64 n][17] pairs along k
    uint32_t* Bl = Bh + 64 * 17;
    __nv_bfloat16* Bhb = (__nv_bfloat16*)Bh;
    __nv_bfloat16* Blb = (__nv_bfloat16*)Bl;

    const int tid  = threadIdx.x;
    const int lane = tid & 31;
    const int wid  = tid >> 5;
    const int g  = lane >> 2, tg = lane & 3;
    const int wm = wid & 1, wn = wid >> 1;     // 2 (m) x 4 (n)

    const int bx    = blockIdx.x;
    const int which = bx / nblk;
    const int bxl   = bx - which * nblk;
    const int col0  = bxl * 64;                  // within selected B
    const int ocol0 = which * N + col0;          // within C
    const int row0  = blockIdx.y * 64;
    const float* Bm = (which == 0) ? B0 : (which == 1) ? B1 : B2;
    const int epi   = (which == 0) ? e0 : (which == 1) ? e1 : e2;

    float acc[2][2][4];
#pragma unroll
    for (int a = 0; a < 2; a++)
#pragma unroll
        for (int b = 0; b < 2; b++)
#pragma unroll
            for (int c = 0; c < 4; c++) acc[a][b][c] = 0.f;

    for (int kt = 0; kt < Kd; kt += 32) {
        __syncthreads();
        // A tile 64x32 -> Ah/Al packed pairs (2 float4 per thread)
#pragma unroll
        for (int it = 0; it < 2; it++) {
            int flat = it * 256 + tid;
            int m  = flat >> 3;
            int kq = (flat & 7) << 2;
            float4 av = *(const float4*)(A + (size_t)(row0 + m) * Kd + kt + kq);
            __nv_bfloat16 h0, l0, h1, l1, h2, l2, h3, l3;
            split_bf(av.x, h0, l0); split_bf(av.y, h1, l1);
            split_bf(av.z, h2, l2); split_bf(av.w, h3, l3);
            int base = m * 17 + (kq >> 1);
            Ah[base]     = pack_bf2(__bfloat162float(h0), __bfloat162float(h1));
            Ah[base + 1] = pack_bf2(__bfloat162float(h2), __bfloat162float(h3));
            Al[base]     = pack_bf2(__bfloat162float(l0), __bfloat162float(l1));
            Al[base + 1] = pack_bf2(__bfloat162float(l2), __bfloat162float(l3));
        }
        // B tile 32k x 64n -> transposed [n][k] bf16 (2 float4 per thread)
#pragma unroll
        for (int it = 0; it < 2; it++) {
            int flat = it * 256 + tid;
            int kk = flat >> 4;               // k row 0..31
            int nq = (flat & 15) << 2;        // n col
            float4 bv = *(const float4*)(Bm + (size_t)(kt + kk) * N + col0 + nq);
            float vv[4] = {bv.x, bv.y, bv.z, bv.w};
#pragma unroll
            for (int j = 0; j < 4; j++) {
                __nv_bfloat16 h, l; split_bf(vv[j], h, l);
                Bhb[(nq + j) * 34 + kk] = h;
                Blb[(nq + j) * 34 + kk] = l;
            }
        }
        __syncthreads();

#pragma unroll
        for (int ks = 0; ks < 2; ks++) {        // two k16 slices
            int kb = ks * 8;
            uint32_t ah[2][4], al[2][4];
#pragma unroll
            for (int mt = 0; mt < 2; mt++) {
                int r = wm * 32 + mt * 16;
                ah[mt][0] = Ah[(r + g) * 17 + kb + tg];
                ah[mt][1] = Ah[(r + g + 8) * 17 + kb + tg];
                ah[mt][2] = Ah[(r + g) * 17 + kb + tg + 4];
                ah[mt][3] = Ah[(r + g + 8) * 17 + kb + tg + 4];
                al[mt][0] = Al[(r + g) * 17 + kb + tg];
                al[mt][1] = Al[(r + g + 8) * 17 + kb + tg];
                al[mt][2] = Al[(r + g) * 17 + kb + tg + 4];
                al[mt][3] = Al[(r + g + 8) * 17 + kb + tg + 4];
            }
#pragma unroll
            for (int nt = 0; nt < 2; nt++) {
                int c = wn * 16 + nt * 8;
                uint32_t bh0 = Bh[(c + g) * 17 + kb + tg];
                uint32_t bh1 = Bh[(c + g) * 17 + kb + tg + 4];
                uint32_t bl0 = Bl[(c + g) * 17 + kb + tg];
                uint32_t bl1 = Bl[(c + g) * 17 + kb + tg + 4];
#pragma unroll
                for (int mt = 0; mt < 2; mt++) {
                    mma16(acc[mt][nt], ah[mt], bh0, bh1);
                    mma16(acc[mt][nt], al[mt], bh0, bh1);
                    mma16(acc[mt][nt], ah[mt], bl0, bl1);
                }
            }
        }
    }

    float sp = (epi == 2) ? log1pf(expf(dts[kidx])) : 0.f;
#pragma unroll
    for (int mt = 0; mt < 2; mt++) {
#pragma unroll
        for (int nt = 0; nt < 2; nt++) {
            int r = row0 + wm * 32 + mt * 16 + g;
            int c = ocol0 + wn * 16 + nt * 8 + 2 * tg;
#pragma unroll
            for (int e = 0; e < 4; e++) {
                int rr = r + (e >> 1) * 8;
                int cc = c + (e & 1);
                size_t o = (size_t)rr * ldc + cc;
                float x = acc[mt][nt][e];
                float y;
                if (epi == 1)      y = (x > 0.f) ? (x + 1.f) : expf(x);
                else if (epi == 2) y = aux[o] + sp * x;
                else if (epi == 3) y = aux[o] + x;
                else               y = x;
                C[o] = y;
            }
        }
    }
}

// ============================================================================
// bf16x3 attention: per (b,h,q64): S = pq@pk^T, W = relu(S)^2, C = W@v,
// out = C/(rowsum+1) - v.  pq/pk/v strided (QKVS) from fused buffer.
// ============================================================================
#define ATT_SMEM ((4 * 64 * 17 + 2 * 32 * 33 + 64 * 68 + 256 + 64) * 4)

__global__ void __launch_bounds__(256)
attn_tc(const float* __restrict__ pq_, const float* __restrict__ pk_,
        const float* __restrict__ v_, float* __restrict__ cmv)
{
    extern __shared__ uint32_t sh[];
    uint32_t* qh = sh;                  // [64][17] pairs along dh
    uint32_t* ql = qh + 64 * 17;
    uint32_t* kh = ql + 64 * 17;        // [64 tok][17] pairs along dh
    uint32_t* kl = kh + 64 * 17;
    uint32_t* vh = kl + 64 * 17;        // [32 dh][33] pairs along token
    uint32_t* vl = vh + 32 * 33;
    float* Ssm  = (float*)(vl + 32 * 33);  // 64 x 68
    float* ssum = Ssm + 64 * 68;           // 256
    float* sinv = ssum + 256;              // 64
    __nv_bfloat16* vhb = (__nv_bfloat16*)vh;
    __nv_bfloat16* vlb = (__nv_bfloat16*)vl;

    const int tid  = threadIdx.x;
    const int lane = tid & 31, wid = tid >> 5;
    const int g = lane >> 2, tg = lane & 3;
    const int wm = wid & 1, wn = wid >> 1;   // 2 (m) x 4 (n)
    const int bh = blockIdx.x;
    const int b = bh >> 3, h = bh & 7;
    const int qb = blockIdx.y;

    // load pq tile (64 x 32), split+pack
#pragma unroll
    for (int it = 0; it < 2; it++) {
        int flat = it * 256 + tid;
        int r  = flat >> 3;
        int dq = (flat & 7) << 2;
        float4 av = *(const float4*)(pq_ + (size_t)(b * N_ + qb * 64 + r) * QKVS + h * DH_ + dq);
        __nv_bfloat16 h0, l0, h1, l1, h2, l2, h3, l3;
        split_bf(av.x, h0, l0); split_bf(av.y, h1, l1);
        split_bf(av.z, h2, l2); split_bf(av.w, h3, l3);
        int base = r * 17 + (dq >> 1);
        qh[base]     = pack_bf2(__bfloat162float(h0), __bfloat162float(h1));
        qh[base + 1] = pack_bf2(__bfloat162float(h2), __bfloat162float(h3));
        ql[base]     = pack_bf2(__bfloat162float(l0), __bfloat162float(l1));
        ql[base + 1] = pack_bf2(__bfloat162float(l2), __bfloat162float(l3));
    }

    float cacc[2][4];
#pragma unroll
    for (int mt = 0; mt < 2; mt++)
#pragma unroll
        for (int e = 0; e < 4; e++) cacc[mt][e] = 0.f;
    float srow = 0.f;
    const int myrow = tid >> 2, myq = tid & 3;

    for (int kt = 0; kt < N_; kt += 64) {
        __syncthreads();
        // load pk (pairs along dh) and v (transposed: pairs along token)
#pragma unroll
        for (int it = 0; it < 2; it++) {
            int flat = it * 256 + tid;
            int r  = flat >> 3;
            int dq = (flat & 7) << 2;
            size_t go = (size_t)(b * N_ + kt + r) * QKVS + h * DH_ + dq;
            float4 kv4 = *(const float4*)(pk_ + go);
            float4 vv4 = *(const float4*)(v_ + go);
            {
                __nv_bfloat16 h0, l0, h1, l1, h2, l2, h3, l3;
                split_bf(kv4.x, h0, l0); split_bf(kv4.y, h1, l1);
                split_bf(kv4.z, h2, l2); split_bf(kv4.w, h3, l3);
                int base = r * 17 + (dq >> 1);
                kh[base]     = pack_bf2(__bfloat162float(h0), __bfloat162float(h1));
                kh[base + 1] = pack_bf2(__bfloat162float(h2), __bfloat162float(h3));
                kl[base]     = pack_bf2(__bfloat162float(l0), __bfloat162float(l1));
                kl[base + 1] = pack_bf2(__bfloat162float(l2), __bfloat162float(l3));
            }
            {
                float vv[4] = {vv4.x, vv4.y, vv4.z, vv4.w};
#pragma unroll
                for (int j = 0; j < 4; j++) {
                    __nv_bfloat16 hh, ll; split_bf(vv[j], hh, ll);
                    vhb[(dq + j) * 66 + r] = hh;
                    vlb[(dq + j) * 66 + r] = ll;
                }
            }
        }
        __syncthreads();

        // phase 1: S = pq @ pk^T, warp tile 32x16
        float sacc[2][2][4];
#pragma unroll
        for (int mt = 0; mt < 2; mt++)
#pragma unroll
            for (int nt = 0; nt < 2; nt++)
#pragma unroll
                for (int e = 0; e < 4; e++) sacc[mt][nt][e] = 0.f;

#pragma unroll
        for (int ks = 0; ks < 2; ks++) {        // dh = 32 -> two k16 slices
            int kb = ks * 8;
            uint32_t ah[2][4], al[2][4];
#pragma unroll
            for (int mt = 0; mt < 2; mt++) {
                int r = wm * 32 + mt * 16;
                ah[mt][0] = qh[(r + g) * 17 + kb + tg];
                ah[mt][1] = qh[(r + g + 8) * 17 + kb + tg];
                ah[mt][2] = qh[(r + g) * 17 + kb + tg + 4];
                ah[mt][3] = qh[(r + g + 8) * 17 + kb + tg + 4];
                al[mt][0] = ql[(r + g) * 17 + kb + tg];
                al[mt][1] = ql[(r + g + 8) * 17 + kb + tg];
                al[mt][2] = ql[(r + g) * 17 + kb + tg + 4];
                al[mt][3] = ql[(r + g + 8) * 17 + kb + tg + 4];
            }
#pragma unroll
            for (int nt = 0; nt < 2; nt++) {
                int c = wn * 16 + nt * 8;
                uint32_t bh0 = kh[(c + g) * 17 + kb + tg];
                uint32_t bh1 = kh[(c + g) * 17 + kb + tg + 4];
                uint32_t bl0 = kl[(c + g) * 17 + kb + tg];
                uint32_t bl1 = kl[(c + g) * 17 + kb + tg + 4];
#pragma unroll
                for (int mt = 0; mt < 2; mt++) {
                    mma16(sacc[mt][nt], ah[mt], bh0, bh1);
                    mma16(sacc[mt][nt], al[mt], bh0, bh1);
                    mma16(sacc[mt][nt], ah[mt], bl0, bl1);
                }
            }
        }
        // relu^2 -> Ssm
#pragma unroll
        for (int mt = 0; mt < 2; mt++)
#pragma unroll
            for (int nt = 0; nt < 2; nt++) {
                int r = wm * 32 + mt * 16 + g;
                int c = wn * 16 + nt * 8 + 2 * tg;
#pragma unroll
                for (int e = 0; e < 4; e++) {
                    int rr = r + (e >> 1) * 8, cc = c + (e & 1);
                    float w = fmaxf(sacc[mt][nt][e], 0.f);
                    Ssm[rr * 68 + cc] = w * w;
                }
            }
        __syncthreads();

        // rowsum partial
        {
            const float* spp = Ssm + myrow * 68 + myq * 16;
            float t = 0.f;
#pragma unroll
            for (int j = 0; j < 16; j++) t += spp[j];
            srow += t;
        }

        // phase 2: C += P @ v, warp tile 32 rows x 8 dh cols
#pragma unroll
        for (int ks = 0; ks < 4; ks++) {       // token = 64 -> four k16 slices
            int kb = ks * 16;
            uint32_t ah2[2][4], al2[2][4];
#pragma unroll
            for (int mt = 0; mt < 2; mt++) {
                int r = wm * 32 + mt * 16;
                const float* S0 = Ssm + (r + g) * 68 + kb;
                const float* S1 = Ssm + (r + g + 8) * 68 + kb;
                float f0a = S0[2 * tg],     f0b = S0[2 * tg + 1];
                float f1a = S1[2 * tg],     f1b = S1[2 * tg + 1];
                float f2a = S0[2 * tg + 8], f2b = S0[2 * tg + 9];
                float f3a = S1[2 * tg + 8], f3b = S1[2 * tg + 9];
                __nv_bfloat16 hh, ll;
                float h0a, l0a, h0b, l0b;
                split_bf(f0a, hh, ll); h0a = __bfloat162float(hh); l0a = __bfloat162float(ll);
                split_bf(f0b, hh, ll); h0b = __bfloat162float(hh); l0b = __bfloat162float(ll);
                ah2[mt][0] = pack_bf2(h0a, h0b); al2[mt][0] = pack_bf2(l0a, l0b);
                split_bf(f1a, hh, ll); h0a = __bfloat162float(hh); l0a = __bfloat162float(ll);
                split_bf(f1b, hh, ll); h0b = __bfloat162float(hh); l0b = __bfloat162float(ll);
                ah2[mt][1] = pack_bf2(h0a, h0b); al2[mt][1] = pack_bf2(l0a, l0b);
                split_bf(f2a, hh, ll); h0a = __bfloat162float(hh); l0a = __bfloat162float(ll);
                split_bf(f2b, hh, ll); h0b = __bfloat162float(hh); l0b = __bfloat162float(ll);
                ah2[mt][2] = pack_bf2(h0a, h0b); al2[mt][2] = pack_bf2(l0a, l0b);
                split_bf(f3a, hh, ll); h0a = __bfloat162float(hh); l0a = __bfloat162float(ll);
                split_bf(f3b, hh, ll); h0b = __bfloat162float(hh); l0b = __bfloat162float(ll);
                ah2[mt][3] = pack_bf2(h0a, h0b); al2[mt][3] = pack_bf2(l0a, l0b);
            }
            int c = wn * 8;
            uint32_t bh0 = vh[(c + g) * 33 + ks * 8 + tg];
            uint32_t bh1 = vh[(c + g) * 33 + ks * 8 + tg + 4];
            uint32_t bl0 = vl[(c + g) * 33 + ks * 8 + tg];
            uint32_t bl1 = vl[(c + g) * 33 + ks * 8 + tg + 4];
#pragma unroll
            for (int mt = 0; mt < 2; mt++) {
                mma16(cacc[mt], ah2[mt], bh0, bh1);
                mma16(cacc[mt], al2[mt], bh0, bh1);
                mma16(cacc[mt], ah2[mt], bl0, bl1);
            }
        }
    }

    // rowsum reduce
    ssum[myrow * 4 + myq] = srow;
    __syncthreads();
    if (tid < 64) {
        float s = ssum[tid * 4] + ssum[tid * 4 + 1] + ssum[tid * 4 + 2] + ssum[tid * 4 + 3];
        sinv[tid] = 1.f / (s + 1.f);
    }
    __syncthreads();

    // epilogue: out = C * inv - v
#pragma unroll
    for (int mt = 0; mt < 2; mt++) {
        int rl = wm * 32 + mt * 16 + g;
        int cl = wn * 8 + 2 * tg;
#pragma unroll
        for (int e = 0; e < 4; e++) {
            int rr = rl + (e >> 1) * 8;
            int cc = cl + (e & 1);
            size_t vo = (size_t)(b * N_ + qb * 64 + rr) * QKVS + h * DH_ + cc;
            size_t oo = (size_t)(b * N_ + qb * 64 + rr) * D_ + h * DH_ + cc;
            cmv[oo] = cacc[mt][e] * sinv[rr] - v_[vo];
        }
    }
}

// ============================================================================
// tf32 x1 GEMM (LM head only): 128x64x32 tiles
// ============================================================================
#define GEMM_SMEM_1 (((128 * 33) + (32 * 65)) * 4)

__global__ void __launch_bounds__(256, 2)
gemm_lm(const float* __restrict__ A, const float* __restrict__ Bm, float* __restrict__ C,
        int N, int Kd)
{
    extern __shared__ uint32_t sh[];
    uint32_t* Ah = sh;                      // 128*33
    uint32_t* Bh = Ah + 128 * 33;           // 32*65

    const int tid  = threadIdx.x;
    const int lane = tid & 31;
    const int wid  = tid >> 5;
    const int g  = lane >> 2, tg = lane & 3;
    const int wm = wid & 3,   wn = wid >> 2;          // 4 (m) x 2 (n)
    const int row0 = blockIdx.y * 128;
    const int col0 = blockIdx.x * 64;

    float acc[2][4][4];
#pragma unroll
    for (int a = 0; a < 2; a++)
#pragma unroll
        for (int b = 0; b < 4; b++)
#pragma unroll
            for (int c = 0; c < 4; c++) acc[a][b][c] = 0.f;

    for (int kt = 0; kt < Kd; kt += 32) {
        __syncthreads();
#pragma unroll
        for (int it = 0; it < 4; it++) {
            int flat = it * 256 + tid;
            int m  = flat >> 3;
            int kq = (flat & 7) << 2;
            float4 av = *(const float4*)(A + (size_t)(row0 + m) * Kd + kt + kq);
            float vv[4] = {av.x, av.y, av.z, av.w};
#pragma unroll
            for (int j = 0; j < 4; j++) {
                uint32_t hi, lo; split2(vv[j], hi, lo);
                Ah[m * 33 + kq + j] = hi;
            }
        }
#pragma unroll
        for (int it = 0; it < 2; it++) {
            int flat = it * 256 + tid;
            int kk = flat >> 4;
            int nq = (flat & 15) << 2;
            float4 bv = *(const float4*)(Bm + (size_t)(kt + kk) * N + col0 + nq);
            float vv[4] = {bv.x, bv.y, bv.z, bv.w};
#pragma unroll
            for (int j = 0; j < 4; j++) {
                uint32_t hi, lo; split2(vv[j], hi, lo);
                Bh[kk * 65 + nq + j] = hi;
            }
        }
        __syncthreads();

#pragma unroll
        for (int ks = 0; ks < 4; ks++) {
            int kb = ks * 8;
            uint32_t ah[2][4];
#pragma unroll
            for (int mt = 0; mt < 2; mt++) {
                int r = wm * 32 + mt * 16;
                ah[mt][0] = Ah[(r + g) * 33 + kb + tg];
                ah[mt][1] = Ah[(r + g + 8) * 33 + kb + tg];
                ah[mt][2] = Ah[(r + g) * 33 + kb + tg + 4];
                ah[mt][3] = Ah[(r + g + 8) * 33 + kb + tg + 4];
            }
#pragma unroll
            for (int nt = 0; nt < 4; nt++) {
                int c = wn * 32 + nt * 8;
                uint32_t bh0 = Bh[(kb + tg) * 65 + c + g];
                uint32_t bh1 = Bh[(kb + tg + 4) * 65 + c + g];
#pragma unroll
                for (int mt = 0; mt < 2; mt++) mma8(acc[mt][nt], ah[mt], bh0, bh1);
            }
        }
    }

#pragma unroll
    for (int mt = 0; mt < 2; mt++) {
#pragma unroll
        for (int nt = 0; nt < 4; nt++) {
            int r = row0 + wm * 32 + mt * 16 + g;
            int c = col0 + wn * 32 + nt * 8 + 2 * tg;
#pragma unroll
            for (int e = 0; e < 4; e++) {
                int rr = r + (e >> 1) * 8;
                int cc = c + (e & 1);
                C[(size_t)rr * N + cc] = acc[mt][nt][e];
            }
        }
    }
}

// ---------------- fused silu-gate + depthwise conv3 ----------------
__global__ void siluconv_kernel(const float* __restrict__ gu, const float* __restrict__ cw,
                                int kidx, float* __restrict__ out) {
    int idx = blockIdx.x * 256 + threadIdx.x;
    int i   = idx & (IN_ - 1);
    int bn  = idx >> 10;
    int n   = bn & (N_ - 1);
    const float* wp = cw + ((size_t)kidx * IN_ + i) * CK_;

    float gC = gu[(size_t)bn * (2 * IN_) + i];
    float uC = gu[(size_t)bn * (2 * IN_) + IN_ + i];
    float a = wp[1] * (gC / (1.f + expf(-gC)) * uC);
    if (n > 0) {
        float gm = gu[(size_t)(bn - 1) * (2 * IN_) + i];
        float um = gu[(size_t)(bn - 1) * (2 * IN_) + IN_ + i];
        a = fmaf(wp[0], gm / (1.f + expf(-gm)) * um, a);
    }
    if (n < N_ - 1) {
        float gp = gu[(size_t)(bn + 1) * (2 * IN_) + i];
        float up = gu[(size_t)(bn + 1) * (2 * IN_) + IN_ + i];
        a = fmaf(wp[2], gp / (1.f + expf(-gp)) * up, a);
    }
    out[idx] = a;
}

// ---------------- halt head ----------------
__global__ void halt_kernel(const float* __restrict__ qn, const float* __restrict__ hw,
                            const float* __restrict__ hb, float* __restrict__ out, int l4) {
    int b = blockIdx.x;
    int d = threadIdx.x;
    float s = 0.f;
    for (int n = 0; n < N_; n++) s += qn[(size_t)(b * N_ + n) * D_ + d];
    float p = (s * (1.f / N_)) * hw[d];
    float tot = blockReduceSum256(p);
    if (threadIdx.x == 0)
        out[l4 * B_ + b] = 1.f / (1.f + expf(-(tot + hb[0])));
}

// ---------------- host orchestration ----------------
static inline float* symaddr(const void* sym) {
    void* p = nullptr;
    cudaGetSymbolAddress(&p, sym);
    return (float*)p;
}

extern "C" void kernel_launch(void* const* d_in, const int* in_sizes, int n_in,
                              void* d_out, int out_size) {
    const int*   ids   = (const int*)  d_in[0];
    const float* emb   = (const float*)d_in[1];
    const float* pos   = (const float*)d_in[2];
    const float* in_w  = (const float*)d_in[3];
    const float* in_b  = (const float*)d_in[4];
    const float* Wq    = (const float*)d_in[5];
    const float* Wk    = (const float*)d_in[6];
    const float* Wv    = (const float*)d_in[7];
    const float* Wo    = (const float*)d_in[8];
    const float* dts   = (const float*)d_in[9];
    const float* Wup   = (const float*)d_in[10];
    const float* cw    = (const float*)d_in[11];
    const float* Wd    = (const float*)d_in[12];
    const float* n1w   = (const float*)d_in[13];
    const float* n1b   = (const float*)d_in[14];
    const float* n2w   = (const float*)d_in[15];
    const float* n2b   = (const float*)d_in[16];
    const float* fin_w = (const float*)d_in[17];
    const float* fin_b = (const float*)d_in[18];
    const float* haltw = (const float*)d_in[19];
    const float* haltb = (const float*)d_in[20];
    const float* lm_w  = (const float*)d_in[21];

    float* out        = (float*)d_out;
    float* out_logits = out;
    float* out_halts  = out + (size_t)out_size - (size_t)(MAXL_ - TRUNC_) * B_;

    float* pX   = symaddr(g_X);
    float* pQ   = symaddr(g_Q);
    float* pHc  = symaddr(g_Hc);
    float* pQKV = symaddr(g_qkv);
    float* pCmv = symaddr(g_cmv);
    float* pHn  = symaddr(g_hn);
    float* pGU  = symaddr(g_gu);
    float* pHc2 = symaddr(g_hc2);
    float* pQn  = symaddr(g_qn);

    cudaFuncSetAttribute(gemm_b3, cudaFuncAttributeMaxDynamicSharedMemorySize, GB3_SMEM);
    cudaFuncSetAttribute(attn_tc, cudaFuncAttributeMaxDynamicSharedMemorySize, ATT_SMEM);
    cudaFuncSetAttribute(gemm_lm, cudaFuncAttributeMaxDynamicSharedMemorySize, GEMM_SMEM_1);

    // X = ln(emb[ids] + pos);  Q = X
    embed_kernel<<<BN_, 256>>>(ids, emb, pos, pX);
    ln_kernel<<<BN_, 256>>>(pX, in_w, in_b, nullptr, pX, pQ);

    const dim3 gQKV(12, BN_ / 64);      // 3 matrices x 4 col blocks, 32 row blocks
    const dim3 gDD(4, BN_ / 64);        // N=256
    const dim3 gUP(32, BN_ / 64);       // N=2048
    const dim3 gLM(V_ / 64, BN_ / 128); // (500, 16)
    const int  ec = (BN_ * IN_) / 256;

    for (int l = 0; l < MAXL_; l++) {
        for (int k = 0; k < K_; k++) {
            // Hc = ln(Q; n1) + X
            ln_kernel<<<BN_, 256>>>(pQ, n1w + k * D_, n1b + k * D_, pX, pHc, nullptr);
            // fused qkv: [pq | pk | v] = [elu+1(Hc@Wq) | elu+1(Hc@Wk) | Hc@Wv]
            gemm_b3<<<gQKV, 256, GB3_SMEM>>>(pHc,
                                             Wq + (size_t)k * D_ * D_,
                                             Wk + (size_t)k * D_ * D_,
                                             Wv + (size_t)k * D_ * D_,
                                             pQKV, D_, D_, 4, QKVS,
                                             1, 1, 0, nullptr, nullptr, 0);
            // cmv = (relu(pq pk^T)^2 @ v) / (rowsum + 1) - v
            attn_tc<<<dim3(B_ * H_, N_ / 64), 256, ATT_SMEM>>>(pQKV, pQKV + D_,
                                                               pQKV + 2 * D_, pCmv);
            // Q = Q + softplus(dt_k) * (cmv @ Wo)
            gemm_b3<<<gDD, 256, GB3_SMEM>>>(pCmv, Wo + (size_t)k * D_ * D_,
                                            nullptr, nullptr, pQ, D_, D_, 4, D_,
                                            2, 2, 2, pQ, dts, k);
            // Hn = ln(Q; n2); GU = Hn @ Wup
            ln_kernel<<<BN_, 256>>>(pQ, n2w + k * D_, n2b + k * D_, nullptr, pHn, nullptr);
            gemm_b3<<<gUP, 256, GB3_SMEM>>>(pHn, Wup + (size_t)k * D_ * 2 * IN_,
                                            nullptr, nullptr, pGU, D_, 2 * IN_, 32, 2 * IN_,
                                            0, 0, 0, nullptr, nullptr, 0);
            // Hc2 = conv3(silu(G)*U); Q = Q + Hc2 @ Wd
            siluconv_kernel<<<ec, 256>>>(pGU, cw, k, pHc2);
            gemm_b3<<<gDD, 256, GB3_SMEM>>>(pHc2, Wd + (size_t)k * IN_ * D_,
                                            nullptr, nullptr, pQ, IN_, D_, 4, D_,
                                            3, 3, 3, pQ, nullptr, 0);
        }
        if (l >= TRUNC_) {
            int l4 = l - TRUNC_;
            ln_kernel<<<BN_, 256>>>(pQ, fin_w, fin_b, nullptr, pQn, nullptr);
            halt_kernel<<<B_, 256>>>(pQn, haltw, haltb, out_halts, l4);
            gemm_lm<<<gLM, 256, GEMM_SMEM_1>>>(pQn, lm_w,
                                               out_logits + (size_t)l4 * BN_ * V_,
                                               V_, D_);
        }
    }
}

// round 8
// speedup vs baseline: 1.6476x; 1.6476x over previous
#include <cuda_runtime.h>
#include <cuda_bf16.h>
#include <math.h>
#include <stdint.h>

// ---------------- model constants ----------------
#define B_    2
#define N_    1024
#define D_    256
#define H_    8
#define DH_   32
#define K_    4
#define IN_   1024
#define V_    32000
#define CK_   3
#define MAXL_ 8
#define TRUNC_ 4
#define BN_   (B_ * N_)

// ---------------- fp32 scratch ----------------
__device__ float g_X [BN_ * D_];
__device__ float g_Q [BN_ * D_];
__device__ float g_gu[BN_ * 2 * IN_];
__device__ float g_qn[BN_ * D_];

// ---------------- activation split planes (bf16 hi/lo) ----------------
__device__ __align__(16) __nv_bfloat16 g_hc_h [BN_ * D_],     g_hc_l [BN_ * D_];
__device__ __align__(16) __nv_bfloat16 g_qkv_h[BN_ * 3 * D_], g_qkv_l[BN_ * 3 * D_];
__device__ __align__(16) __nv_bfloat16 g_cmv_h[BN_ * D_],     g_cmv_l[BN_ * D_];
__device__ __align__(16) __nv_bfloat16 g_hn_h [BN_ * D_],     g_hn_l [BN_ * D_];
__device__ __align__(16) __nv_bfloat16 g_hc2_h[BN_ * IN_],    g_hc2_l[BN_ * IN_];
__device__ __align__(16) __nv_bfloat16 g_qn_h [BN_ * D_],     g_qn_l [BN_ * D_];

// ---------------- transposed split weights [n][k] (bf16 hi/lo) --------
__device__ __align__(16) __nv_bfloat16 g_wq_h [K_ * D_ * D_],      g_wq_l [K_ * D_ * D_];
__device__ __align__(16) __nv_bfloat16 g_wk_h [K_ * D_ * D_],      g_wk_l [K_ * D_ * D_];
__device__ __align__(16) __nv_bfloat16 g_wv_h [K_ * D_ * D_],      g_wv_l [K_ * D_ * D_];
__device__ __align__(16) __nv_bfloat16 g_wo_h [K_ * D_ * D_],      g_wo_l [K_ * D_ * D_];
__device__ __align__(16) __nv_bfloat16 g_wup_h[K_ * 2 * IN_ * D_], g_wup_l[K_ * 2 * IN_ * D_];
__device__ __align__(16) __nv_bfloat16 g_wd_h [K_ * D_ * IN_],     g_wd_l [K_ * D_ * IN_];
__device__ __align__(16) __nv_bfloat16 g_lm_h [(size_t)V_ * D_],   g_lm_l [(size_t)V_ * D_];

// ---------------- helpers ----------------
__device__ __forceinline__ void split_bf(float v, __nv_bfloat16& h, __nv_bfloat16& l) {
    h = __float2bfloat16_rn(v);
    l = __float2bfloat16_rn(v - __bfloat162float(h));
}
__device__ __forceinline__ uint32_t pack2f(float a, float b) {
    __nv_bfloat162 t = __floats2bfloat162_rn(a, b);
    return *reinterpret_cast<uint32_t*>(&t);
}
__device__ __forceinline__ uint32_t sptr(const void* p) {
    return (uint32_t)__cvta_generic_to_shared(p);
}
__device__ __forceinline__ void ldsm4(uint32_t* r, uint32_t sa) {
    asm volatile("ldmatrix.sync.aligned.m8n8.x4.shared.b16 {%0,%1,%2,%3}, [%4];"
                 : "=r"(r[0]), "=r"(r[1]), "=r"(r[2]), "=r"(r[3]) : "r"(sa));
}
__device__ __forceinline__ void ldsm4t(uint32_t* r, uint32_t sa) {
    asm volatile("ldmatrix.sync.aligned.m8n8.x4.trans.shared.b16 {%0,%1,%2,%3}, [%4];"
                 : "=r"(r[0]), "=r"(r[1]), "=r"(r[2]), "=r"(r[3]) : "r"(sa));
}
__device__ __forceinline__ void mma16(float* c, const uint32_t* a, uint32_t b0, uint32_t b1) {
    asm volatile("mma.sync.aligned.m16n8k16.row.col.f32.bf16.bf16.f32 "
                 "{%0,%1,%2,%3}, {%4,%5,%6,%7}, {%8,%9}, {%0,%1,%2,%3};"
                 : "+f"(c[0]), "+f"(c[1]), "+f"(c[2]), "+f"(c[3])
                 : "r"(a[0]), "r"(a[1]), "r"(a[2]), "r"(a[3]), "r"(b0), "r"(b1));
}

__device__ __forceinline__ float blockReduceSum256(float v) {
    __shared__ float sh[8];
    int lane = threadIdx.x & 31;
    int wid  = threadIdx.x >> 5;
#pragma unroll
    for (int o = 16; o > 0; o >>= 1) v += __shfl_down_sync(0xffffffffu, v, o);
    __syncthreads();
    if (lane == 0) sh[wid] = v;
    __syncthreads();
    float t = 0.f;
#pragma unroll
    for (int i = 0; i < 8; i++) t += sh[i];
    return t;
}

// ---------------- weight transpose + split:  W[k][n] -> out[n][k] hi/lo --------
__global__ void tsplit(const float* __restrict__ W, __nv_bfloat16* __restrict__ oh,
                       __nv_bfloat16* __restrict__ ol, int Kd, int Nn)
{
    __shared__ float t[32][33];
    const float* Wz = W + (size_t)blockIdx.z * Kd * Nn;
    __nv_bfloat16* ohz = oh + (size_t)blockIdx.z * Kd * Nn;
    __nv_bfloat16* olz = ol + (size_t)blockIdx.z * Kd * Nn;
    int n0 = blockIdx.x * 32, k0 = blockIdx.y * 32;
    int tx = threadIdx.x, ty = threadIdx.y;          // 32 x 8
#pragma unroll
    for (int i = 0; i < 4; i++)
        t[ty + i * 8][tx] = Wz[(size_t)(k0 + ty + i * 8) * Nn + n0 + tx];
    __syncthreads();
#pragma unroll
    for (int i = 0; i < 4; i++) {
        int n = ty + i * 8;
        float v = t[tx][n];
        __nv_bfloat16 hh, ll; split_bf(v, hh, ll);
        ohz[(size_t)(n0 + n) * Kd + k0 + tx] = hh;
        olz[(size_t)(n0 + n) * Kd + k0 + tx] = ll;
    }
}

// ---------------- embedding + positional ----------------
__global__ void embed_kernel(const int* __restrict__ ids,
                             const float* __restrict__ emb,
                             const float* __restrict__ pos,
                             float* __restrict__ X) {
    int row = blockIdx.x;
    int d   = threadIdx.x;
    int n   = row & (N_ - 1);
    int id  = ids[row];
    X[(size_t)row * D_ + d] = emb[(size_t)id * D_ + d] + pos[(size_t)n * D_ + d];
}

// ---------------- layernorm fp32 out (initial) ----------------
__global__ void ln_kernel(const float* __restrict__ in,
                          const float* __restrict__ w,
                          const float* __restrict__ b,
                          float* __restrict__ out,
                          float* __restrict__ out2) {
    int row = blockIdx.x;
    int d   = threadIdx.x;
    float x  = in[(size_t)row * D_ + d];
    float mu = blockReduceSum256(x) * (1.f / D_);
    float dx = x - mu;
    float var = blockReduceSum256(dx * dx) * (1.f / D_);
    float y = dx * rsqrtf(var + 1e-5f) * w[d] + b[d];
    out[(size_t)row * D_ + d] = y;
    if (out2) out2[(size_t)row * D_ + d] = y;
}

// ---------------- layernorm -> split planes (+ optional residual / fp32 copy) --
__global__ void ln_split(const float* __restrict__ in,
                         const float* __restrict__ w,
                         const float* __restrict__ b,
                         const float* __restrict__ addX,
                         __nv_bfloat16* __restrict__ oh,
                         __nv_bfloat16* __restrict__ ol,
                         float* __restrict__ ofp) {
    int row = blockIdx.x;
    int d   = threadIdx.x;
    float x  = in[(size_t)row * D_ + d];
    float mu = blockReduceSum256(x) * (1.f / D_);
    float dx = x - mu;
    float var = blockReduceSum256(dx * dx) * (1.f / D_);
    float y = dx * rsqrtf(var + 1e-5f) * w[d] + b[d];
    if (addX) y += addX[(size_t)row * D_ + d];
    __nv_bfloat16 hh, ll; split_bf(y, hh, ll);
    oh[(size_t)row * D_ + d] = hh;
    ol[(size_t)row * D_ + d] = ll;
    if (ofp) ofp[(size_t)row * D_ + d] = y;
}

// ============================================================================
// gemm_bs: C[M, nmats*nblk*64] = epi(A @ B^T), pre-split bf16 planes both sides
//   64x64x64 tiles, 8 warps (2m x 4n), ldmatrix, bf16x3.
// MODE: 0 fp32 store; 2 aux + softplus(dts[kidx])*x; 3 aux + x;
//       4 split-plane store (elu+1 when which<2)   [QKV]
// ============================================================================
#define GS_PAD  72
#define GS_SMEM (4 * 64 * GS_PAD * 2)

template <int MODE>
__global__ void __launch_bounds__(256)
gemm_bs(const __nv_bfloat16* __restrict__ Agh, const __nv_bfloat16* __restrict__ Agl,
        const __nv_bfloat16* __restrict__ B0h, const __nv_bfloat16* __restrict__ B0l,
        const __nv_bfloat16* __restrict__ B1h, const __nv_bfloat16* __restrict__ B1l,
        const __nv_bfloat16* __restrict__ B2h, const __nv_bfloat16* __restrict__ B2l,
        int Kd, int nblk,
        float* __restrict__ Cf, int ldc,
        __nv_bfloat16* __restrict__ Oh, __nv_bfloat16* __restrict__ Ol, int ldo,
        const float* __restrict__ aux, const float* __restrict__ dts, int kidx)
{
    extern __shared__ __nv_bfloat16 sm[];
    __nv_bfloat16* Ash = sm;
    __nv_bfloat16* Asl = Ash + 64 * GS_PAD;
    __nv_bfloat16* Bsh = Asl + 64 * GS_PAD;
    __nv_bfloat16* Bsl = Bsh + 64 * GS_PAD;

    const int tid  = threadIdx.x;
    const int lane = tid & 31, wid = tid >> 5;
    const int g = lane >> 2, tg = lane & 3;
    const int mi = lane >> 3, ri = lane & 7;
    const int wm = wid & 1, wn = wid >> 1;           // 2(m) x 4(n)
    const int which = blockIdx.x / nblk;
    const int bxl   = blockIdx.x - which * nblk;
    const int col0  = bxl * 64;
    const int row0  = blockIdx.y * 64;
    const __nv_bfloat16* Bgh = (which == 0) ? B0h : (which == 1) ? B1h : B2h;
    const __nv_bfloat16* Bgl = (which == 0) ? B0l : (which == 1) ? B1l : B2l;

    float acc[2][2][4];
#pragma unroll
    for (int a = 0; a < 2; a++)
#pragma unroll
        for (int b = 0; b < 2; b++)
#pragma unroll
            for (int c = 0; c < 4; c++) acc[a][b][c] = 0.f;

    for (int kt = 0; kt < Kd; kt += 64) {
        __syncthreads();
#pragma unroll
        for (int it = 0; it < 2; it++) {
            int f  = it * 256 + tid;
            int r  = f >> 3;
            int c8 = (f & 7) * 8;
            *(uint4*)(Ash + r * GS_PAD + c8) = *(const uint4*)(Agh + (size_t)(row0 + r) * Kd + kt + c8);
            *(uint4*)(Asl + r * GS_PAD + c8) = *(const uint4*)(Agl + (size_t)(row0 + r) * Kd + kt + c8);
            *(uint4*)(Bsh + r * GS_PAD + c8) = *(const uint4*)(Bgh + (size_t)(col0 + r) * Kd + kt + c8);
            *(uint4*)(Bsl + r * GS_PAD + c8) = *(const uint4*)(Bgl + (size_t)(col0 + r) * Kd + kt + c8);
        }
        __syncthreads();

#pragma unroll
        for (int ks = 0; ks < 4; ks++) {
            int kb = ks * 16;
            uint32_t ah[2][4], al[2][4];
#pragma unroll
            for (int mt = 0; mt < 2; mt++) {
                int row = wm * 32 + mt * 16 + (mi & 1) * 8 + ri;
                int col = kb + (mi >> 1) * 8;
                ldsm4(ah[mt], sptr(Ash + row * GS_PAD + col));
                ldsm4(al[mt], sptr(Asl + row * GS_PAD + col));
            }
            int rowb = wn * 16 + (mi >> 1) * 8 + ri;
            int colb = kb + (mi & 1) * 8;
            uint32_t bh[4], bl[4];
            ldsm4(bh, sptr(Bsh + rowb * GS_PAD + colb));
            ldsm4(bl, sptr(Bsl + rowb * GS_PAD + colb));
#pragma unroll
            for (int nt = 0; nt < 2; nt++)
#pragma unroll
                for (int mt = 0; mt < 2; mt++) {
                    mma16(acc[mt][nt], ah[mt], bh[2 * nt], bh[2 * nt + 1]);
                    mma16(acc[mt][nt], al[mt], bh[2 * nt], bh[2 * nt + 1]);
                    mma16(acc[mt][nt], ah[mt], bl[2 * nt], bl[2 * nt + 1]);
                }
        }
    }

    float sp = 0.f;
    if (MODE == 2) sp = log1pf(expf(dts[kidx]));
    const int ocolbase = which * (nblk * 64) + col0;
#pragma unroll
    for (int mt = 0; mt < 2; mt++)
#pragma unroll
        for (int nt = 0; nt < 2; nt++)
#pragma unroll
            for (int e = 0; e < 4; e++) {
                int r = row0 + wm * 32 + mt * 16 + g + ((e >> 1) ? 8 : 0);
                int c = ocolbase + wn * 16 + nt * 8 + 2 * tg + (e & 1);
                float x = acc[mt][nt][e];
                if (MODE == 4) {
                    float y = (which < 2) ? ((x > 0.f) ? (x + 1.f) : expf(x)) : x;
                    __nv_bfloat16 hh, ll; split_bf(y, hh, ll);
                    Oh[(size_t)r * ldo + c] = hh;
                    Ol[(size_t)r * ldo + c] = ll;
                } else {
                    size_t o = (size_t)r * ldc + c;
                    if (MODE == 2)      Cf[o] = aux[o] + sp * x;
                    else if (MODE == 3) Cf[o] = aux[o] + x;
                    else                Cf[o] = x;
                }
            }
}

// ============================================================================
// attn_bs: flash-style bf16x3. Block = 64 q rows x (b,h); 8 warps, two
// warp-groups split the kt stream. Warp owns 16 q-rows x 64 k-cols -> P in regs.
// out = (relu(pq pk^T)^2 @ v)/(rowsum+1) - v, emitted as split planes.
// ============================================================================
#define AT_PAD  40
#define AT_SMEM ((2 + 8) * 64 * AT_PAD * 2 + (4 * 32 * 16 + 4 * 32 * 2) * 4)

__global__ void __launch_bounds__(256)
attn_bs(const __nv_bfloat16* __restrict__ qkvh, const __nv_bfloat16* __restrict__ qkvl,
        __nv_bfloat16* __restrict__ cmvh, __nv_bfloat16* __restrict__ cmvl)
{
    extern __shared__ __nv_bfloat16 smb[];
    __nv_bfloat16* qh = smb;
    __nv_bfloat16* ql = qh + 64 * AT_PAD;
    __nv_bfloat16* kv = ql + 64 * AT_PAD;                 // 8 planes [64][AT_PAD]
    float* cred = (float*)(kv + 8 * 64 * AT_PAD);         // [128][16]
    float* sred = cred + 4 * 32 * 16;                     // [128][2]

    const int tid  = threadIdx.x;
    const int lane = tid & 31, wid = tid >> 5;
    const int w4 = wid & 3, wg = wid >> 2;
    const int g = lane >> 2, tg = lane & 3;
    const int mi = lane >> 3, ri = lane & 7;
    const int b = blockIdx.x >> 3, h = blockIdx.x & 7;
    const int qb = blockIdx.y;
    const size_t qrow0 = (size_t)(b * N_ + qb * 64);

    // stage q planes
#pragma unroll
    for (int it = 0; it < 2; it++) {
        int f  = it * 256 + tid;
        int pl = f >> 8;
        int r  = (f >> 2) & 63;
        int j  = f & 3;
        const __nv_bfloat16* src = (pl ? qkvl : qkvh) + (qrow0 + r) * (3 * D_) + h * DH_ + j * 8;
        *(uint4*)((pl ? ql : qh) + r * AT_PAD + j * 8) = *(const uint4*)src;
    }
    __syncthreads();

    // q fragments (persist)
    uint32_t qfh[2][4], qfl[2][4];
    {
        int row = w4 * 16 + (mi & 1) * 8 + ri;
#pragma unroll
        for (int ks = 0; ks < 2; ks++) {
            int col = ks * 16 + (mi >> 1) * 8;
            ldsm4(qfh[ks], sptr(qh + row * AT_PAD + col));
            ldsm4(qfl[ks], sptr(ql + row * AT_PAD + col));
        }
    }

    float cacc[4][4];
#pragma unroll
    for (int nt = 0; nt < 4; nt++)
#pragma unroll
        for (int e = 0; e < 4; e++) cacc[nt][e] = 0.f;
    float sr0 = 0.f, sr1 = 0.f;

    __nv_bfloat16* mykv = kv + wg * 4 * 64 * AT_PAD;

    for (int t = 0; t < 8; t++) {
        __syncthreads();
        // stage 2 kt tiles x 4 planes (khi,klo,vhi,vlo)
#pragma unroll
        for (int it = 0; it < 8; it++) {
            int f = it * 256 + tid;
            int p = f >> 8;                 // 0..7: buf = p>>2, sub = p&3
            int sub = p & 3;
            int r = (f >> 2) & 63;
            int j = f & 3;
            int colofs = ((sub < 2) ? D_ : 2 * D_) + h * DH_;
            const __nv_bfloat16* srcp = (sub & 1) ? qkvl : qkvh;
            size_t row = (size_t)(b * N_ + (2 * t + (p >> 2)) * 64 + r);
            *(uint4*)(kv + p * 64 * AT_PAD + r * AT_PAD + j * 8) =
                *(const uint4*)(srcp + row * (3 * D_) + colofs + j * 8);
        }
        __syncthreads();

        const __nv_bfloat16* khp = mykv;
        const __nv_bfloat16* klp = mykv + 64 * AT_PAD;
        const __nv_bfloat16* vhp = mykv + 2 * 64 * AT_PAD;
        const __nv_bfloat16* vlp = mykv + 3 * 64 * AT_PAD;

        // ---- phase 1: S = pq @ pk^T (16 q rows x 64 k cols) ----
        float sacc[8][4];
#pragma unroll
        for (int nt = 0; nt < 8; nt++)
#pragma unroll
            for (int e = 0; e < 4; e++) sacc[nt][e] = 0.f;

#pragma unroll
        for (int ks = 0; ks < 2; ks++) {
            int kb = ks * 16;
#pragma unroll
            for (int np = 0; np < 4; np++) {
                int rown = np * 16 + (mi >> 1) * 8 + ri;
                int coln = kb + (mi & 1) * 8;
                uint32_t bh[4], bl[4];
                ldsm4(bh, sptr(khp + rown * AT_PAD + coln));
                ldsm4(bl, sptr(klp + rown * AT_PAD + coln));
                mma16(sacc[np * 2 + 0], qfh[ks], bh[0], bh[1]);
                mma16(sacc[np * 2 + 0], qfl[ks], bh[0], bh[1]);
                mma16(sacc[np * 2 + 0], qfh[ks], bl[0], bl[1]);
                mma16(sacc[np * 2 + 1], qfh[ks], bh[2], bh[3]);
                mma16(sacc[np * 2 + 1], qfl[ks], bh[2], bh[3]);
                mma16(sacc[np * 2 + 1], qfh[ks], bl[2], bl[3]);
            }
        }
        // relu^2 + rowsum partials
#pragma unroll
        for (int nt = 0; nt < 8; nt++) {
#pragma unroll
            for (int e = 0; e < 4; e++) {
                float w = fmaxf(sacc[nt][e], 0.f);
                sacc[nt][e] = w * w;
            }
            sr0 += sacc[nt][0] + sacc[nt][1];
            sr1 += sacc[nt][2] + sacc[nt][3];
        }

        // ---- phase 2: C += P @ v (P fragments straight from sacc) ----
#pragma unroll
        for (int ks2 = 0; ks2 < 4; ks2++) {
            uint32_t ph[4], pl4[4];
            {
                float r0 = sacc[2 * ks2][0],     r1 = sacc[2 * ks2][1];
                float r2 = sacc[2 * ks2][2],     r3 = sacc[2 * ks2][3];
                float r4 = sacc[2 * ks2 + 1][0], r5 = sacc[2 * ks2 + 1][1];
                float r6 = sacc[2 * ks2 + 1][2], r7 = sacc[2 * ks2 + 1][3];
                __nv_bfloat16 h0, l0, h1, l1;
                split_bf(r0, h0, l0); split_bf(r1, h1, l1);
                ph[0] = pack2f(__bfloat162float(h0), __bfloat162float(h1));
                pl4[0] = pack2f(__bfloat162float(l0), __bfloat162float(l1));
                split_bf(r2, h0, l0); split_bf(r3, h1, l1);
                ph[1] = pack2f(__bfloat162float(h0), __bfloat162float(h1));
                pl4[1] = pack2f(__bfloat162float(l0), __bfloat162float(l1));
                split_bf(r4, h0, l0); split_bf(r5, h1, l1);
                ph[2] = pack2f(__bfloat162float(h0), __bfloat162float(h1));
                pl4[2] = pack2f(__bfloat162float(l0), __bfloat162float(l1));
                split_bf(r6, h0, l0); split_bf(r7, h1, l1);
                ph[3] = pack2f(__bfloat162float(h0), __bfloat162float(h1));
                pl4[3] = pack2f(__bfloat162float(l0), __bfloat162float(l1));
            }
            int rowv = ks2 * 16 + (mi & 1) * 8 + ri;
#pragma unroll
            for (int dp = 0; dp < 2; dp++) {
                int colv = (dp * 2 + (mi >> 1)) * 8;
                uint32_t bh[4], bl[4];
                ldsm4t(bh, sptr(vhp + rowv * AT_PAD + colv));
                ldsm4t(bl, sptr(vlp + rowv * AT_PAD + colv));
                mma16(cacc[dp * 2 + 0], ph, bh[0], bh[1]);
                mma16(cacc[dp * 2 + 0], pl4, bh[0], bh[1]);
                mma16(cacc[dp * 2 + 0], ph, bl[0], bl[1]);
                mma16(cacc[dp * 2 + 1], ph, bh[2], bh[3]);
                mma16(cacc[dp * 2 + 1], pl4, bh[2], bh[3]);
                mma16(cacc[dp * 2 + 1], ph, bl[2], bl[3]);
            }
        }
    }

    // ---- combine two warp-groups ----
    __syncthreads();
    if (wg == 1) {
        float* cd = cred + (w4 * 32 + lane) * 16;
#pragma unroll
        for (int nt = 0; nt < 4; nt++)
#pragma unroll
            for (int e = 0; e < 4; e++) cd[nt * 4 + e] = cacc[nt][e];
        sred[(w4 * 32 + lane) * 2 + 0] = sr0;
        sred[(w4 * 32 + lane) * 2 + 1] = sr1;
    }
    __syncthreads();
    if (wg == 0) {
        const float* cd = cred + (w4 * 32 + lane) * 16;
#pragma unroll
        for (int nt = 0; nt < 4; nt++)
#pragma unroll
            for (int e = 0; e < 4; e++) cacc[nt][e] += cd[nt * 4 + e];
        sr0 += sred[(w4 * 32 + lane) * 2 + 0];
        sr1 += sred[(w4 * 32 + lane) * 2 + 1];
        sr0 += __shfl_xor_sync(0xffffffffu, sr0, 1);
        sr0 += __shfl_xor_sync(0xffffffffu, sr0, 2);
        sr1 += __shfl_xor_sync(0xffffffffu, sr1, 1);
        sr1 += __shfl_xor_sync(0xffffffffu, sr1, 2);
        float inv0 = 1.f / (sr0 + 1.f);
        float inv1 = 1.f / (sr1 + 1.f);

#pragma unroll
        for (int nt = 0; nt < 4; nt++)
#pragma unroll
            for (int e = 0; e < 4; e++) {
                int rl = w4 * 16 + g + ((e >> 1) ? 8 : 0);
                int dh = nt * 8 + 2 * tg + (e & 1);
                size_t row = qrow0 + rl;
                size_t vof = row * (3 * D_) + 2 * D_ + h * DH_ + dh;
                float vv = __bfloat162float(qkvh[vof]) + __bfloat162float(qkvl[vof]);
                float y = cacc[nt][e] * ((e >> 1) ? inv1 : inv0) - vv;
                __nv_bfloat16 hh, ll; split_bf(y, hh, ll);
                cmvh[row * D_ + h * DH_ + dh] = hh;
                cmvl[row * D_ + h * DH_ + dh] = ll;
            }
    }
}

// ---------------- fused silu-gate + depthwise conv3 -> split planes ----------
__global__ void siluconv_split(const float* __restrict__ gu, const float* __restrict__ cw,
                               int kidx, __nv_bfloat16* __restrict__ oh,
                               __nv_bfloat16* __restrict__ ol) {
    int idx = blockIdx.x * 256 + threadIdx.x;
    int i   = idx & (IN_ - 1);
    int bn  = idx >> 10;
    int n   = bn & (N_ - 1);
    const float* wp = cw + ((size_t)kidx * IN_ + i) * CK_;

    float gC = gu[(size_t)bn * (2 * IN_) + i];
    float uC = gu[(size_t)bn * (2 * IN_) + IN_ + i];
    float a = wp[1] * (gC / (1.f + expf(-gC)) * uC);
    if (n > 0) {
        float gm = gu[(size_t)(bn - 1) * (2 * IN_) + i];
        float um = gu[(size_t)(bn - 1) * (2 * IN_) + IN_ + i];
        a = fmaf(wp[0], gm / (1.f + expf(-gm)) * um, a);
    }
    if (n < N_ - 1) {
        float gp = gu[(size_t)(bn + 1) * (2 * IN_) + i];
        float up = gu[(size_t)(bn + 1) * (2 * IN_) + IN_ + i];
        a = fmaf(wp[2], gp / (1.f + expf(-gp)) * up, a);
    }
    __nv_bfloat16 hh, ll; split_bf(a, hh, ll);
    oh[idx] = hh;
    ol[idx] = ll;
}

// ---------------- halt head ----------------
__global__ void halt_kernel(const float* __restrict__ qn, const float* __restrict__ hw,
                            const float* __restrict__ hb, float* __restrict__ out, int l4) {
    int b = blockIdx.x;
    int d = threadIdx.x;
    float s = 0.f;
    for (int n = 0; n < N_; n++) s += qn[(size_t)(b * N_ + n) * D_ + d];
    float p = (s * (1.f / N_)) * hw[d];
    float tot = blockReduceSum256(p);
    if (threadIdx.x == 0)
        out[l4 * B_ + b] = 1.f / (1.f + expf(-(tot + hb[0])));
}

// ---------------- host orchestration ----------------
static inline void* symp(const void* sym) {
    void* p = nullptr;
    cudaGetSymbolAddress(&p, sym);
    return p;
}

extern "C" void kernel_launch(void* const* d_in, const int* in_sizes, int n_in,
                              void* d_out, int out_size) {
    const int*   ids   = (const int*)  d_in[0];
    const float* emb   = (const float*)d_in[1];
    const float* pos   = (const float*)d_in[2];
    const float* in_w  = (const float*)d_in[3];
    const float* in_b  = (const float*)d_in[4];
    const float* Wq    = (const float*)d_in[5];
    const float* Wk    = (const float*)d_in[6];
    const float* Wv    = (const float*)d_in[7];
    const float* Wo    = (const float*)d_in[8];
    const float* dts   = (const float*)d_in[9];
    const float* Wup   = (const float*)d_in[10];
    const float* cw    = (const float*)d_in[11];
    const float* Wd    = (const float*)d_in[12];
    const float* n1w   = (const float*)d_in[13];
    const float* n1b   = (const float*)d_in[14];
    const float* n2w   = (const float*)d_in[15];
    const float* n2b   = (const float*)d_in[16];
    const float* fin_w = (const float*)d_in[17];
    const float* fin_b = (const float*)d_in[18];
    const float* haltw = (const float*)d_in[19];
    const float* haltb = (const float*)d_in[20];
    const float* lm_w  = (const float*)d_in[21];

    float* out        = (float*)d_out;
    float* out_logits = out;
    float* out_halts  = out + (size_t)out_size - (size_t)(MAXL_ - TRUNC_) * B_;

    float* pX  = (float*)symp(g_X);
    float* pQ  = (float*)symp(g_Q);
    float* pGU = (float*)symp(g_gu);
    float* pQn = (float*)symp(g_qn);

    __nv_bfloat16* pHcH = (__nv_bfloat16*)symp(g_hc_h),  *pHcL = (__nv_bfloat16*)symp(g_hc_l);
    __nv_bfloat16* pQkH = (__nv_bfloat16*)symp(g_qkv_h), *pQkL = (__nv_bfloat16*)symp(g_qkv_l);
    __nv_bfloat16* pCmH = (__nv_bfloat16*)symp(g_cmv_h), *pCmL = (__nv_bfloat16*)symp(g_cmv_l);
    __nv_bfloat16* pHnH = (__nv_bfloat16*)symp(g_hn_h),  *pHnL = (__nv_bfloat16*)symp(g_hn_l);
    __nv_bfloat16* pH2H = (__nv_bfloat16*)symp(g_hc2_h), *pH2L = (__nv_bfloat16*)symp(g_hc2_l);
    __nv_bfloat16* pQnH = (__nv_bfloat16*)symp(g_qn_h),  *pQnL = (__nv_bfloat16*)symp(g_qn_l);

    __nv_bfloat16* pWqH = (__nv_bfloat16*)symp(g_wq_h),  *pWqL = (__nv_bfloat16*)symp(g_wq_l);
    __nv_bfloat16* pWkH = (__nv_bfloat16*)symp(g_wk_h),  *pWkL = (__nv_bfloat16*)symp(g_wk_l);
    __nv_bfloat16* pWvH = (__nv_bfloat16*)symp(g_wv_h),  *pWvL = (__nv_bfloat16*)symp(g_wv_l);
    __nv_bfloat16* pWoH = (__nv_bfloat16*)symp(g_wo_h),  *pWoL = (__nv_bfloat16*)symp(g_wo_l);
    __nv_bfloat16* pWuH = (__nv_bfloat16*)symp(g_wup_h), *pWuL = (__nv_bfloat16*)symp(g_wup_l);
    __nv_bfloat16* pWdH = (__nv_bfloat16*)symp(g_wd_h),  *pWdL = (__nv_bfloat16*)symp(g_wd_l);
    __nv_bfloat16* pLmH = (__nv_bfloat16*)symp(g_lm_h),  *pLmL = (__nv_bfloat16*)symp(g_lm_l);

    cudaFuncSetAttribute(gemm_bs<0>, cudaFuncAttributeMaxDynamicSharedMemorySize, GS_SMEM);
    cudaFuncSetAttribute(gemm_bs<2>, cudaFuncAttributeMaxDynamicSharedMemorySize, GS_SMEM);
    cudaFuncSetAttribute(gemm_bs<3>, cudaFuncAttributeMaxDynamicSharedMemorySize, GS_SMEM);
    cudaFuncSetAttribute(gemm_bs<4>, cudaFuncAttributeMaxDynamicSharedMemorySize, GS_SMEM);
    cudaFuncSetAttribute(attn_bs,    cudaFuncAttributeMaxDynamicSharedMemorySize, AT_SMEM);

    // -------- weight prep (transpose + bf16 split) --------
    const dim3 tb(32, 8);
    tsplit<<<dim3(8, 8, 4),    tb>>>(Wq,   pWqH, pWqL, D_,  D_);
    tsplit<<<dim3(8, 8, 4),    tb>>>(Wk,   pWkH, pWkL, D_,  D_);
    tsplit<<<dim3(8, 8, 4),    tb>>>(Wv,   pWvH, pWvL, D_,  D_);
    tsplit<<<dim3(8, 8, 4),    tb>>>(Wo,   pWoH, pWoL, D_,  D_);
    tsplit<<<dim3(64, 8, 4),   tb>>>(Wup,  pWuH, pWuL, D_,  2 * IN_);
    tsplit<<<dim3(8, 32, 4),   tb>>>(Wd,   pWdH, pWdL, IN_, D_);
    tsplit<<<dim3(1000, 8, 1), tb>>>(lm_w, pLmH, pLmL, D_,  V_);

    // X = ln(emb[ids] + pos); Q = X
    embed_kernel<<<BN_, 256>>>(ids, emb, pos, pX);
    ln_kernel<<<BN_, 256>>>(pX, in_w, in_b, pX, pQ);

    const dim3 gQKV(12, BN_ / 64);      // 3 mats x 4 col blocks
    const dim3 gDD(4, BN_ / 64);
    const dim3 gUP(32, BN_ / 64);
    const dim3 gLM(V_ / 64, BN_ / 64);
    const dim3 gAT(B_ * H_, N_ / 64);
    const int  ec = (BN_ * IN_) / 256;

    for (int l = 0; l < MAXL_; l++) {
        for (int k = 0; k < K_; k++) {
            size_t wo = (size_t)k * D_ * D_;
            // Hc = ln(Q; n1) + X  -> planes
            ln_split<<<BN_, 256>>>(pQ, n1w + k * D_, n1b + k * D_, pX, pHcH, pHcL, nullptr);
            // qkv = [elu+1(Hc@Wq) | elu+1(Hc@Wk) | Hc@Wv] -> planes
            gemm_bs<4><<<gQKV, 256, GS_SMEM>>>(pHcH, pHcL,
                                               pWqH + wo, pWqL + wo,
                                               pWkH + wo, pWkL + wo,
                                               pWvH + wo, pWvL + wo,
                                               D_, 4, nullptr, 0,
                                               pQkH, pQkL, 3 * D_, nullptr, nullptr, 0);
            // cmv planes
            attn_bs<<<gAT, 256, AT_SMEM>>>(pQkH, pQkL, pCmH, pCmL);
            // Q = Q + softplus(dt_k) * (cmv @ Wo)
            gemm_bs<2><<<gDD, 256, GS_SMEM>>>(pCmH, pCmL,
                                              pWoH + wo, pWoL + wo,
                                              pWoH + wo, pWoL + wo,
                                              pWoH + wo, pWoL + wo,
                                              D_, 4, pQ, D_,
                                              nullptr, nullptr, 0, pQ, dts, k);
            // Hn = ln(Q; n2) -> planes; GU = Hn @ Wup (fp32)
            ln_split<<<BN_, 256>>>(pQ, n2w + k * D_, n2b + k * D_, nullptr, pHnH, pHnL, nullptr);
            size_t wu = (size_t)k * D_ * 2 * IN_;
            gemm_bs<0><<<gUP, 256, GS_SMEM>>>(pHnH, pHnL,
                                              pWuH + wu, pWuL + wu,
                                              pWuH + wu, pWuL + wu,
                                              pWuH + wu, pWuL + wu,
                                              D_, 32, pGU, 2 * IN_,
                                              nullptr, nullptr, 0, nullptr, nullptr, 0);
            // Hc2 = conv3(silu(G)*U) -> planes; Q = Q + Hc2 @ Wd
            siluconv_split<<<ec, 256>>>(pGU, cw, k, pH2H, pH2L);
            size_t wd = (size_t)k * IN_ * D_;
            gemm_bs<3><<<gDD, 256, GS_SMEM>>>(pH2H, pH2L,
                                              pWdH + wd, pWdL + wd,
                                              pWdH + wd, pWdL + wd,
                                              pWdH + wd, pWdL + wd,
                                              IN_, 4, pQ, D_,
                                              nullptr, nullptr, 0, pQ, nullptr, 0);
        }
        if (l >= TRUNC_) {
            int l4 = l - TRUNC_;
            ln_split<<<BN_, 256>>>(pQ, fin_w, fin_b, nullptr, pQnH, pQnL, pQn);
            halt_kernel<<<B_, 256>>>(pQn, haltw, haltb, out_halts, l4);
            gemm_bs<0><<<gLM, 256, GS_SMEM>>>(pQnH, pQnL,
                                              pLmH, pLmL, pLmH, pLmL, pLmH, pLmL,
                                              D_, V_ / 64,
                                              out_logits + (size_t)l4 * BN_ * V_, V_,
                                              nullptr, nullptr, 0, nullptr, nullptr, 0);
        }
    }
}